// round 11
// baseline (speedup 1.0000x reference)
#include <cuda_runtime.h>
#include <math.h>

#define NN 50000
#define EE 800000
#define C 64
#define EPSF 1.000001f

// Scratch (device globals: no allocation allowed anywhere).
__device__ __align__(16) float g_xm_l[NN * C];
__device__ __align__(16) float g_xm_u[NN * C];
__device__ float g_ss[4 * NN];   // [s_src_l | s_tgt_l | s_src_u | s_tgt_u]
__device__ __align__(16) float g_v[4 * C];  // [v_sl | v_tl | v_su | v_tu]

// ---------------------------------------------------------------------------
// Kernel 0: v = w @ a_half. 256 threads: tid = vec*64 + k.
// v_sl[k] = sum_o w_l[k][o] * a_l[o];  v_tl uses a_l[64:], etc.
// ---------------------------------------------------------------------------
__global__ void attvec_kernel(const float* __restrict__ w_l,
                              const float* __restrict__ a_l,
                              const float* __restrict__ w_u,
                              const float* __restrict__ a_u) {
    int vec = threadIdx.x >> 6;   // 0..3
    int k   = threadIdx.x & 63;
    const float* w = (vec < 2) ? w_l : w_u;
    const float* a = (vec < 2) ? a_l : a_u;
    const float* ah = a + (vec & 1) * C;
    float s = 0.f;
#pragma unroll
    for (int o = 0; o < C; o++)
        s = fmaf(w[k * C + o], ah[o], s);
    g_v[vec * C + k] = s;
}

// ---------------------------------------------------------------------------
// Kernel A: three fused GEMMs (no epilogue). 64x64 tile, 4x4 thread tile.
// __launch_bounds__(256,2) caps regs at 128 -> 2 CTAs/SM.
// ---------------------------------------------------------------------------
__global__ __launch_bounds__(256, 2) void gemm3_v4_kernel(
        const float* __restrict__ x,
        const float* __restrict__ w_l,
        const float* __restrict__ w_u,
        const float* __restrict__ w_lin,
        float* __restrict__ out) {
    __shared__ float xs[64][64];

    int tid = threadIdx.x;
    int ct = tid & 15;          // col-thread
    int rt = tid >> 4;          // row-thread
    int c0 = ct * 4;
    int rowbase = blockIdx.x * 64 + rt * 4;

#pragma unroll
    for (int v = 0; v < 4; v++) {
        int f = tid + v * 256;          // float4 index in [0,1024)
        int r = f >> 4, c4 = f & 15;
        int grow = blockIdx.x * 64 + r;
        float4 val = make_float4(0.f, 0.f, 0.f, 0.f);
        if (grow < NN)
            val = *reinterpret_cast<const float4*>(x + (size_t)grow * C + c4 * 4);
        *reinterpret_cast<float4*>(&xs[r][c4 * 4]) = val;
    }
    __syncthreads();

    float4 al[4], au[4], aw[4];
#pragma unroll
    for (int rr = 0; rr < 4; rr++) {
        al[rr] = make_float4(0.f, 0.f, 0.f, 0.f);
        au[rr] = make_float4(0.f, 0.f, 0.f, 0.f);
        aw[rr] = make_float4(0.f, 0.f, 0.f, 0.f);
    }

#pragma unroll 4
    for (int k = 0; k < C; k++) {
        float4 wl = *reinterpret_cast<const float4*>(w_l   + k * C + c0);
        float4 wu = *reinterpret_cast<const float4*>(w_u   + k * C + c0);
        float4 ww = *reinterpret_cast<const float4*>(w_lin + k * C + c0);
#pragma unroll
        for (int rr = 0; rr < 4; rr++) {
            float xv = xs[rt * 4 + rr][k];
            al[rr].x = fmaf(xv, wl.x, al[rr].x);
            al[rr].y = fmaf(xv, wl.y, al[rr].y);
            al[rr].z = fmaf(xv, wl.z, al[rr].z);
            al[rr].w = fmaf(xv, wl.w, al[rr].w);
            au[rr].x = fmaf(xv, wu.x, au[rr].x);
            au[rr].y = fmaf(xv, wu.y, au[rr].y);
            au[rr].z = fmaf(xv, wu.z, au[rr].z);
            au[rr].w = fmaf(xv, wu.w, au[rr].w);
            aw[rr].x = fmaf(xv, ww.x, aw[rr].x);
            aw[rr].y = fmaf(xv, ww.y, aw[rr].y);
            aw[rr].z = fmaf(xv, ww.z, aw[rr].z);
            aw[rr].w = fmaf(xv, ww.w, aw[rr].w);
        }
    }

#pragma unroll
    for (int rr = 0; rr < 4; rr++) {
        int row = rowbase + rr;
        if (row < NN) {
            size_t o = (size_t)row * C + c0;
            *reinterpret_cast<float4*>(g_xm_l + o) = al[rr];
            *reinterpret_cast<float4*>(g_xm_u + o) = au[rr];
            float4 w4 = aw[rr];
            w4.x *= EPSF; w4.y *= EPSF; w4.z *= EPSF; w4.w *= EPSF;
            *reinterpret_cast<float4*>(out + o) = w4;
        }
    }
}

// ---------------------------------------------------------------------------
// Kernel B: attention scalars via s = x @ v. One warp per row.
// Lane holds x[row][2*lane..2*lane+1]; 4 dots; shfl reduce.
// ---------------------------------------------------------------------------
__global__ void scalars_v2_kernel(const float* __restrict__ x) {
    int warp = (blockIdx.x * blockDim.x + threadIdx.x) >> 5;
    int lane = threadIdx.x & 31;
    if (warp >= NN) return;

    float2 xr = *reinterpret_cast<const float2*>(x + (size_t)warp * C + lane * 2);
    float2 v0 = *reinterpret_cast<const float2*>(g_v          + lane * 2);
    float2 v1 = *reinterpret_cast<const float2*>(g_v + C      + lane * 2);
    float2 v2 = *reinterpret_cast<const float2*>(g_v + 2 * C  + lane * 2);
    float2 v3 = *reinterpret_cast<const float2*>(g_v + 3 * C  + lane * 2);

    float s0 = xr.x * v0.x + xr.y * v0.y;
    float s1 = xr.x * v1.x + xr.y * v1.y;
    float s2 = xr.x * v2.x + xr.y * v2.y;
    float s3 = xr.x * v3.x + xr.y * v3.y;
#pragma unroll
    for (int off = 16; off > 0; off >>= 1) {
        s0 += __shfl_xor_sync(0xFFFFFFFFu, s0, off);
        s1 += __shfl_xor_sync(0xFFFFFFFFu, s1, off);
        s2 += __shfl_xor_sync(0xFFFFFFFFu, s2, off);
        s3 += __shfl_xor_sync(0xFFFFFFFFu, s3, off);
    }
    if (lane == 0) {
        g_ss[warp]          = s0;
        g_ss[NN + warp]     = s1;
        g_ss[2 * NN + warp] = s2;
        g_ss[3 * NN + warp] = s3;
    }
}

// ---------------------------------------------------------------------------
// Kernel C: fused edge scatter (lower + upper per edge).
// 16 threads/edge; lane 0 computes both alphas, broadcast via shfl.
// Gathers use __ldcg (L2-resident, no L1 reuse).
// ---------------------------------------------------------------------------
__global__ void edge_fused_kernel(const int* __restrict__ l_idx,
                                  const float* __restrict__ l_vals,
                                  const int* __restrict__ u_idx,
                                  const float* __restrict__ u_vals,
                                  float* __restrict__ out) {
    int t = blockIdx.x * blockDim.x + threadIdx.x;
    int e = t >> 4;
    if (e >= EE) return;
    int lane16 = t & 15;
    int part = lane16 * 4;

    int il = 0, jl = 0, iu = 0, ju = 0;
    float al = 0.f, au = 0.f;
    if (lane16 == 0) {
        il = l_idx[e];  jl = l_idx[EE + e];
        iu = u_idx[e];  ju = u_idx[EE + e];
        float sl = g_ss[jl]          + g_ss[NN + il];
        float su = g_ss[2 * NN + ju] + g_ss[3 * NN + iu];
        sl = (sl > 0.f) ? sl : expm1f(sl);
        su = (su > 0.f) ? su : expm1f(su);
        al = sl * l_vals[e];
        au = su * u_vals[e];
    }
    il = __shfl_sync(0xFFFFFFFFu, il, 0, 16);
    jl = __shfl_sync(0xFFFFFFFFu, jl, 0, 16);
    iu = __shfl_sync(0xFFFFFFFFu, iu, 0, 16);
    ju = __shfl_sync(0xFFFFFFFFu, ju, 0, 16);
    al = __shfl_sync(0xFFFFFFFFu, al, 0, 16);
    au = __shfl_sync(0xFFFFFFFFu, au, 0, 16);

    float4 ml = __ldcg(reinterpret_cast<const float4*>(g_xm_l + (size_t)jl * C + part));
    float4 mu = __ldcg(reinterpret_cast<const float4*>(g_xm_u + (size_t)ju * C + part));

    float* pl = out + (size_t)il * C + part;
    asm volatile("red.global.add.v4.f32 [%0], {%1, %2, %3, %4};"
                 :: "l"(pl), "f"(al * ml.x), "f"(al * ml.y),
                    "f"(al * ml.z), "f"(al * ml.w) : "memory");
    float* pu = out + (size_t)iu * C + part;
    asm volatile("red.global.add.v4.f32 [%0], {%1, %2, %3, %4};"
                 :: "l"(pu), "f"(au * mu.x), "f"(au * mu.y),
                    "f"(au * mu.z), "f"(au * mu.w) : "memory");
}

// ---------------------------------------------------------------------------
// Kernel D: in-place ReLU on d_out.
// ---------------------------------------------------------------------------
__global__ void relu_kernel(float* __restrict__ out) {
    int t = blockIdx.x * blockDim.x + threadIdx.x;
    if (t >= NN * C / 4) return;
    float4* p = reinterpret_cast<float4*>(out) + t;
    float4 v = *p;
    v.x = fmaxf(v.x, 0.f);
    v.y = fmaxf(v.y, 0.f);
    v.z = fmaxf(v.z, 0.f);
    v.w = fmaxf(v.w, 0.f);
    *p = v;
}

// ---------------------------------------------------------------------------
extern "C" void kernel_launch(void* const* d_in, const int* in_sizes, int n_in,
                              void* d_out, int out_size) {
    const float* x      = (const float*)d_in[0];
    const int*   l_idx  = (const int*)d_in[1];
    const float* l_vals = (const float*)d_in[2];
    const int*   u_idx  = (const int*)d_in[3];
    const float* u_vals = (const float*)d_in[4];
    const float* w_l    = (const float*)d_in[5];
    const float* a_l    = (const float*)d_in[6];
    const float* w_u    = (const float*)d_in[7];
    const float* a_u    = (const float*)d_in[8];
    const float* w_lin  = (const float*)d_in[9];
    float* out = (float*)d_out;

    // 0: attention projection vectors v = w @ a_half
    attvec_kernel<<<1, 256>>>(w_l, a_l, w_u, a_u);

    // A: GEMMs (64 rows/block, 4x4 thread tiles, occ-capped regs)
    gemm3_v4_kernel<<<(NN + 63) / 64, 256>>>(x, w_l, w_u, w_lin, out);

    // B: attention scalars s = x @ v (warp per row)
    scalars_v2_kernel<<<(NN + 7) / 8, 256>>>(x);

    // C: fused edge scatter (16 threads/edge, both branches)
    int eblocks = (EE * 16) / 256;  // exact: 50000
    edge_fused_kernel<<<eblocks, 256>>>(l_idx, l_vals, u_idx, u_vals, out);

    // D: ReLU in place
    relu_kernel<<<(NN * C / 4 + 255) / 256, 256>>>(out);
}

// round 12
// speedup vs baseline: 1.0020x; 1.0020x over previous
#include <cuda_runtime.h>
#include <math.h>

#define NN 50000
#define EE 800000
#define C 64
#define EPSF 1.000001f

// Scratch (device globals: no allocation allowed anywhere).
__device__ __align__(16) float g_xm_l[NN * C];
__device__ __align__(16) float g_xm_u[NN * C];
__device__ float g_ss[4 * NN];   // [s_src_l | s_tgt_l | s_src_u | s_tgt_u]
__device__ __align__(16) float g_v[4 * C];  // [v_sl | v_tl | v_su | v_tu]

// ---------------------------------------------------------------------------
// Kernel 0: v = w @ a_half. 256 threads: tid = vec*64 + k.
// ---------------------------------------------------------------------------
__global__ void attvec_kernel(const float* __restrict__ w_l,
                              const float* __restrict__ a_l,
                              const float* __restrict__ w_u,
                              const float* __restrict__ a_u) {
    int vec = threadIdx.x >> 6;   // 0..3
    int k   = threadIdx.x & 63;
    const float* w = (vec < 2) ? w_l : w_u;
    const float* a = (vec < 2) ? a_l : a_u;
    const float* ah = a + (vec & 1) * C;
    float s = 0.f;
#pragma unroll
    for (int o = 0; o < C; o++)
        s = fmaf(w[k * C + o], ah[o], s);
    g_v[vec * C + k] = s;
}

// ---------------------------------------------------------------------------
// Kernel A: three fused GEMMs (no epilogue). 64x64 tile, 4x4 thread tile.
// __launch_bounds__(256,2) caps regs at 128 -> 2 CTAs/SM.
// ---------------------------------------------------------------------------
__global__ __launch_bounds__(256, 2) void gemm3_v4_kernel(
        const float* __restrict__ x,
        const float* __restrict__ w_l,
        const float* __restrict__ w_u,
        const float* __restrict__ w_lin,
        float* __restrict__ out) {
    __shared__ float xs[64][64];

    int tid = threadIdx.x;
    int ct = tid & 15;          // col-thread
    int rt = tid >> 4;          // row-thread
    int c0 = ct * 4;
    int rowbase = blockIdx.x * 64 + rt * 4;

#pragma unroll
    for (int v = 0; v < 4; v++) {
        int f = tid + v * 256;          // float4 index in [0,1024)
        int r = f >> 4, c4 = f & 15;
        int grow = blockIdx.x * 64 + r;
        float4 val = make_float4(0.f, 0.f, 0.f, 0.f);
        if (grow < NN)
            val = *reinterpret_cast<const float4*>(x + (size_t)grow * C + c4 * 4);
        *reinterpret_cast<float4*>(&xs[r][c4 * 4]) = val;
    }
    __syncthreads();

    float4 al[4], au[4], aw[4];
#pragma unroll
    for (int rr = 0; rr < 4; rr++) {
        al[rr] = make_float4(0.f, 0.f, 0.f, 0.f);
        au[rr] = make_float4(0.f, 0.f, 0.f, 0.f);
        aw[rr] = make_float4(0.f, 0.f, 0.f, 0.f);
    }

#pragma unroll 4
    for (int k = 0; k < C; k++) {
        float4 wl = *reinterpret_cast<const float4*>(w_l   + k * C + c0);
        float4 wu = *reinterpret_cast<const float4*>(w_u   + k * C + c0);
        float4 ww = *reinterpret_cast<const float4*>(w_lin + k * C + c0);
#pragma unroll
        for (int rr = 0; rr < 4; rr++) {
            float xv = xs[rt * 4 + rr][k];
            al[rr].x = fmaf(xv, wl.x, al[rr].x);
            al[rr].y = fmaf(xv, wl.y, al[rr].y);
            al[rr].z = fmaf(xv, wl.z, al[rr].z);
            al[rr].w = fmaf(xv, wl.w, al[rr].w);
            au[rr].x = fmaf(xv, wu.x, au[rr].x);
            au[rr].y = fmaf(xv, wu.y, au[rr].y);
            au[rr].z = fmaf(xv, wu.z, au[rr].z);
            au[rr].w = fmaf(xv, wu.w, au[rr].w);
            aw[rr].x = fmaf(xv, ww.x, aw[rr].x);
            aw[rr].y = fmaf(xv, ww.y, aw[rr].y);
            aw[rr].z = fmaf(xv, ww.z, aw[rr].z);
            aw[rr].w = fmaf(xv, ww.w, aw[rr].w);
        }
    }

#pragma unroll
    for (int rr = 0; rr < 4; rr++) {
        int row = rowbase + rr;
        if (row < NN) {
            size_t o = (size_t)row * C + c0;
            *reinterpret_cast<float4*>(g_xm_l + o) = al[rr];
            *reinterpret_cast<float4*>(g_xm_u + o) = au[rr];
            float4 w4 = aw[rr];
            w4.x *= EPSF; w4.y *= EPSF; w4.z *= EPSF; w4.w *= EPSF;
            *reinterpret_cast<float4*>(out + o) = w4;
        }
    }
}

// ---------------------------------------------------------------------------
// Kernel B: attention scalars via s = x @ v. One warp per row.
// ---------------------------------------------------------------------------
__global__ void scalars_v2_kernel(const float* __restrict__ x) {
    int warp = (blockIdx.x * blockDim.x + threadIdx.x) >> 5;
    int lane = threadIdx.x & 31;
    if (warp >= NN) return;

    float2 xr = *reinterpret_cast<const float2*>(x + (size_t)warp * C + lane * 2);
    float2 v0 = *reinterpret_cast<const float2*>(g_v          + lane * 2);
    float2 v1 = *reinterpret_cast<const float2*>(g_v + C      + lane * 2);
    float2 v2 = *reinterpret_cast<const float2*>(g_v + 2 * C  + lane * 2);
    float2 v3 = *reinterpret_cast<const float2*>(g_v + 3 * C  + lane * 2);

    float s0 = xr.x * v0.x + xr.y * v0.y;
    float s1 = xr.x * v1.x + xr.y * v1.y;
    float s2 = xr.x * v2.x + xr.y * v2.y;
    float s3 = xr.x * v3.x + xr.y * v3.y;
#pragma unroll
    for (int off = 16; off > 0; off >>= 1) {
        s0 += __shfl_xor_sync(0xFFFFFFFFu, s0, off);
        s1 += __shfl_xor_sync(0xFFFFFFFFu, s1, off);
        s2 += __shfl_xor_sync(0xFFFFFFFFu, s2, off);
        s3 += __shfl_xor_sync(0xFFFFFFFFu, s3, off);
    }
    if (lane == 0) {
        g_ss[warp]          = s0;
        g_ss[NN + warp]     = s1;
        g_ss[2 * NN + warp] = s2;
        g_ss[3 * NN + warp] = s3;
    }
}

// ---------------------------------------------------------------------------
// Kernel C: fused edge scatter (lower + upper per edge).
// 16 threads/edge; lane 0 computes both alphas, broadcast via shfl.
// Gathers are default-cached (L1 reuse: each source row hit ~16x on average).
// ---------------------------------------------------------------------------
__global__ void edge_fused_kernel(const int* __restrict__ l_idx,
                                  const float* __restrict__ l_vals,
                                  const int* __restrict__ u_idx,
                                  const float* __restrict__ u_vals,
                                  float* __restrict__ out) {
    int t = blockIdx.x * blockDim.x + threadIdx.x;
    int e = t >> 4;
    if (e >= EE) return;
    int lane16 = t & 15;
    int part = lane16 * 4;

    int il = 0, jl = 0, iu = 0, ju = 0;
    float al = 0.f, au = 0.f;
    if (lane16 == 0) {
        il = l_idx[e];  jl = l_idx[EE + e];
        iu = u_idx[e];  ju = u_idx[EE + e];
        float sl = g_ss[jl]          + g_ss[NN + il];
        float su = g_ss[2 * NN + ju] + g_ss[3 * NN + iu];
        sl = (sl > 0.f) ? sl : expm1f(sl);
        su = (su > 0.f) ? su : expm1f(su);
        al = sl * l_vals[e];
        au = su * u_vals[e];
    }
    il = __shfl_sync(0xFFFFFFFFu, il, 0, 16);
    jl = __shfl_sync(0xFFFFFFFFu, jl, 0, 16);
    iu = __shfl_sync(0xFFFFFFFFu, iu, 0, 16);
    ju = __shfl_sync(0xFFFFFFFFu, ju, 0, 16);
    al = __shfl_sync(0xFFFFFFFFu, al, 0, 16);
    au = __shfl_sync(0xFFFFFFFFu, au, 0, 16);

    float4 ml = *reinterpret_cast<const float4*>(g_xm_l + (size_t)jl * C + part);
    float4 mu = *reinterpret_cast<const float4*>(g_xm_u + (size_t)ju * C + part);

    float* pl = out + (size_t)il * C + part;
    asm volatile("red.global.add.v4.f32 [%0], {%1, %2, %3, %4};"
                 :: "l"(pl), "f"(al * ml.x), "f"(al * ml.y),
                    "f"(al * ml.z), "f"(al * ml.w) : "memory");
    float* pu = out + (size_t)iu * C + part;
    asm volatile("red.global.add.v4.f32 [%0], {%1, %2, %3, %4};"
                 :: "l"(pu), "f"(au * mu.x), "f"(au * mu.y),
                    "f"(au * mu.z), "f"(au * mu.w) : "memory");
}

// ---------------------------------------------------------------------------
// Kernel D: in-place ReLU on d_out.
// ---------------------------------------------------------------------------
__global__ void relu_kernel(float* __restrict__ out) {
    int t = blockIdx.x * blockDim.x + threadIdx.x;
    if (t >= NN * C / 4) return;
    float4* p = reinterpret_cast<float4*>(out) + t;
    float4 v = *p;
    v.x = fmaxf(v.x, 0.f);
    v.y = fmaxf(v.y, 0.f);
    v.z = fmaxf(v.z, 0.f);
    v.w = fmaxf(v.w, 0.f);
    *p = v;
}

// ---------------------------------------------------------------------------
extern "C" void kernel_launch(void* const* d_in, const int* in_sizes, int n_in,
                              void* d_out, int out_size) {
    const float* x      = (const float*)d_in[0];
    const int*   l_idx  = (const int*)d_in[1];
    const float* l_vals = (const float*)d_in[2];
    const int*   u_idx  = (const int*)d_in[3];
    const float* u_vals = (const float*)d_in[4];
    const float* w_l    = (const float*)d_in[5];
    const float* a_l    = (const float*)d_in[6];
    const float* w_u    = (const float*)d_in[7];
    const float* a_u    = (const float*)d_in[8];
    const float* w_lin  = (const float*)d_in[9];
    float* out = (float*)d_out;

    // 0: attention projection vectors v = w @ a_half
    attvec_kernel<<<1, 256>>>(w_l, a_l, w_u, a_u);

    // A: GEMMs (64 rows/block, 4x4 thread tiles, occ-capped regs)
    gemm3_v4_kernel<<<(NN + 63) / 64, 256>>>(x, w_l, w_u, w_lin, out);

    // B: attention scalars s = x @ v (warp per row)
    scalars_v2_kernel<<<(NN + 7) / 8, 256>>>(x);

    // C: fused edge scatter (16 threads/edge, both branches)
    int eblocks = (EE * 16) / 256;  // exact: 50000
    edge_fused_kernel<<<eblocks, 256>>>(l_idx, l_vals, u_idx, u_vals, out);

    // D: ReLU in place
    relu_kernel<<<(NN * C / 4 + 255) / 256, 256>>>(out);
}